// round 2
// baseline (speedup 1.0000x reference)
#include <cuda_runtime.h>
#include <math.h>

// ---------------- problem constants ----------------
#define BB   256      // batch
#define TT   512      // timesteps
#define HH   1024     // hidden
#define NCTA 128      // persistent CTAs (<= 148 SMs, 1 CTA/SM => co-resident)
#define NTHR 256
#define MT   64       // batch tile per CTA  (4 M-tiles)
#define NT   32       // neuron tile per CTA (32 N-tiles)

// ping-pong hidden state buffers (device globals: no allocation allowed)
__device__ float g_h[2][BB * HH];
// monotonic grid-barrier flags; zero at module load; all end equal after each
// launch, so replays work (each CTA reads its own flag as the phase base).
__device__ volatile int g_flags[NCTA];

__device__ __forceinline__ void fma2(unsigned long long& acc,
                                     unsigned long long a,
                                     unsigned long long b) {
    // packed 2x fp32 FMA (Blackwell FFMA2) — doubles fp32 throughput vs 3-reg FFMA
    asm("fma.rn.f32x2 %0, %1, %2, %0;" : "+l"(acc) : "l"(a), "l"(b));
}

__device__ __forceinline__ float f2sum(unsigned long long a) {
    float lo, hi;
    asm("mov.b64 {%0, %1}, %2;" : "=f"(lo), "=f"(hi) : "l"(a));
    return lo + hi;
}

extern "C" __global__ void __launch_bounds__(NTHR, 1)
rnn_decoder_kernel(const float* __restrict__ init_in,   // [B,1]
                   const float* __restrict__ hidden0,   // [B,H]
                   const float* __restrict__ targets,   // [T,B,1]
                   const float* __restrict__ W_ih,      // [H,1]
                   const float* __restrict__ W_hh,      // [H,H]
                   const float* __restrict__ b_ih,      // [H]
                   const float* __restrict__ b_hh,      // [H]
                   const float* __restrict__ W_out,     // [1,H]
                   const float* __restrict__ b_out,     // [1]
                   float* __restrict__ out)             // [T,B,1]
{
    extern __shared__ float Ws[];          // [NT][HH] fp32 = 128 KB, resident all steps
    __shared__ float y_s[MT];

    const int tid = threadIdx.x;
    const int cta = blockIdx.x;
    const int m   = cta & 3;               // 4 batch tiles of 64
    const int n   = cta >> 2;              // 32 neuron tiles of 32
    const int b0  = m * MT;
    const int i0  = n * NT;
    const int lane = tid & 31;             // lane spans batch
    const int wrp  = tid >> 5;             // warp spans neurons (4 per warp)
    const int bA = b0 + lane;
    const int bBt = b0 + lane + 32;
    const int iBase = i0 + wrp * 4;

    const int base = g_flags[cta];         // phase base (survives replays)
    int phase = 0;

    // ---- init: W_hh slice -> SMEM (coalesced float4) ----
    {
        const float4* src = reinterpret_cast<const float4*>(W_hh + (size_t)i0 * HH);
        float4* dst = reinterpret_cast<float4*>(Ws);
        for (int k = tid; k < NT * HH / 4; k += NTHR) dst[k] = src[k];
    }
    // per-thread constants for my 4 neurons
    float wih_r[4], bsum_r[4], wout_r[4];
#pragma unroll
    for (int q = 0; q < 4; q++) {
        int i = iBase + q;
        wih_r[q]  = W_ih[i];
        bsum_r[q] = b_ih[i] + b_hh[i];
        wout_r[q] = W_out[i];
    }
    const float bo = b_out[0];
    // init out[t][b] = b_out (out is poisoned before timing)
#pragma unroll
    for (int k = 0; k < 4; k++) out[(size_t)cta * 1024 + k * NTHR + tid] = bo;

    // ---- grid barrier (monotonic flags, one-warp poll) ----
    auto gbar = [&]() {
        phase++;
        __syncthreads();                                  // all CTA work done
        if (tid == 0) { __threadfence(); g_flags[cta] = base + phase; }
        if (tid < 32) {
            const int tgt = base + phase;
            bool ok;
            do {
                int a = g_flags[tid];
                int b = g_flags[tid + 32];
                int c = g_flags[tid + 64];
                int d = g_flags[tid + 96];
                ok = (a >= tgt) & (b >= tgt) & (c >= tgt) & (d >= tgt);
            } while (!__all_sync(0xffffffffu, ok));
            __threadfence();                              // acquire
        }
        __syncthreads();
    };

    gbar();   // phase 1: W in SMEM + out initialized, everywhere

    const ulonglong2* __restrict__ w0 =
        reinterpret_cast<const ulonglong2*>(Ws + (wrp * 4 + 0) * HH);
    const ulonglong2* __restrict__ w1 =
        reinterpret_cast<const ulonglong2*>(Ws + (wrp * 4 + 1) * HH);
    const ulonglong2* __restrict__ w2 =
        reinterpret_cast<const ulonglong2*>(Ws + (wrp * 4 + 2) * HH);
    const ulonglong2* __restrict__ w3 =
        reinterpret_cast<const ulonglong2*>(Ws + (wrp * 4 + 3) * HH);

    for (int t = 0; t < TT; t++) {
        const float* hsrc = (t == 0) ? hidden0 : g_h[(t - 1) & 1];
        float*       hdst = g_h[t & 1];
        const float* xsrc = (t == 0) ? init_in : (targets + (size_t)(t - 1) * BB);

        if (tid < MT) y_s[tid] = 0.f;
        __syncthreads();

        const float x0 = xsrc[bA];
        const float x1 = xsrc[bBt];

        const ulonglong2* __restrict__ pA =
            reinterpret_cast<const ulonglong2*>(hsrc + (size_t)bA * HH);
        const ulonglong2* __restrict__ pB =
            reinterpret_cast<const ulonglong2*>(hsrc + (size_t)bBt * HH);

        unsigned long long a00 = 0ull, a01 = 0ull, a02 = 0ull, a03 = 0ull;
        unsigned long long a10 = 0ull, a11 = 0ull, a12 = 0ull, a13 = 0ull;

#pragma unroll 4
        for (int jc = 0; jc < HH / 4; jc++) {
            ulonglong2 ha = pA[jc];                // h[bA][4j..]
            ulonglong2 hb = pB[jc];                // h[bB][4j..]
            ulonglong2 u0 = w0[jc];                // SMEM broadcast within warp
            ulonglong2 u1 = w1[jc];
            ulonglong2 u2 = w2[jc];
            ulonglong2 u3 = w3[jc];
            fma2(a00, ha.x, u0.x); fma2(a00, ha.y, u0.y);
            fma2(a01, ha.x, u1.x); fma2(a01, ha.y, u1.y);
            fma2(a02, ha.x, u2.x); fma2(a02, ha.y, u2.y);
            fma2(a03, ha.x, u3.x); fma2(a03, ha.y, u3.y);
            fma2(a10, hb.x, u0.x); fma2(a10, hb.y, u0.y);
            fma2(a11, hb.x, u1.x); fma2(a11, hb.y, u1.y);
            fma2(a12, hb.x, u2.x); fma2(a12, hb.y, u2.y);
            fma2(a13, hb.x, u3.x); fma2(a13, hb.y, u3.y);
        }

        float h0[4], h1[4];
        h0[0] = tanhf(fmaf(x0, wih_r[0], bsum_r[0]) + f2sum(a00));
        h0[1] = tanhf(fmaf(x0, wih_r[1], bsum_r[1]) + f2sum(a01));
        h0[2] = tanhf(fmaf(x0, wih_r[2], bsum_r[2]) + f2sum(a02));
        h0[3] = tanhf(fmaf(x0, wih_r[3], bsum_r[3]) + f2sum(a03));
        h1[0] = tanhf(fmaf(x1, wih_r[0], bsum_r[0]) + f2sum(a10));
        h1[1] = tanhf(fmaf(x1, wih_r[1], bsum_r[1]) + f2sum(a11));
        h1[2] = tanhf(fmaf(x1, wih_r[2], bsum_r[2]) + f2sum(a12));
        h1[3] = tanhf(fmaf(x1, wih_r[3], bsum_r[3]) + f2sum(a13));

        // store h' (float4, 16B aligned)
        *reinterpret_cast<float4*>(&hdst[(size_t)bA  * HH + iBase]) =
            make_float4(h0[0], h0[1], h0[2], h0[3]);
        *reinterpret_cast<float4*>(&hdst[(size_t)bBt * HH + iBase]) =
            make_float4(h1[0], h1[1], h1[2], h1[3]);

        // output projection partials over my 4 neurons
        float p0 = h0[0] * wout_r[0] + h0[1] * wout_r[1] +
                   h0[2] * wout_r[2] + h0[3] * wout_r[3];
        float p1 = h1[0] * wout_r[0] + h1[1] * wout_r[1] +
                   h1[2] * wout_r[2] + h1[3] * wout_r[3];
        atomicAdd(&y_s[lane], p0);
        atomicAdd(&y_s[lane + 32], p1);
        __syncthreads();
        if (tid < MT) atomicAdd(&out[(size_t)t * BB + b0 + tid], y_s[tid]);

        gbar();   // h' fully published before step t+1 reads it
    }
}

extern "C" void kernel_launch(void* const* d_in, const int* in_sizes, int n_in,
                              void* d_out, int out_size) {
    const float* init_in = (const float*)d_in[0];
    const float* hidden0 = (const float*)d_in[1];
    const float* targets = (const float*)d_in[2];
    const float* W_ih    = (const float*)d_in[3];
    const float* W_hh    = (const float*)d_in[4];
    const float* b_ih    = (const float*)d_in[5];
    const float* b_hh    = (const float*)d_in[6];
    const float* W_out   = (const float*)d_in[7];
    const float* b_out   = (const float*)d_in[8];
    // d_in[9] = teacher_force_probability (== 1, ignored)
    float* out = (float*)d_out;

    const size_t shmem = (size_t)NT * HH * sizeof(float);   // 128 KB
    cudaFuncSetAttribute(rnn_decoder_kernel,
                         cudaFuncAttributeMaxDynamicSharedMemorySize, (int)shmem);
    rnn_decoder_kernel<<<NCTA, NTHR, shmem>>>(init_in, hidden0, targets, W_ih,
                                              W_hh, b_ih, b_hh, W_out, b_out,
                                              out);
}

// round 3
// speedup vs baseline: 2.5898x; 2.5898x over previous
#include <cuda_runtime.h>
#include <math.h>

// ---------------- problem constants ----------------
#define BB   256      // batch
#define TT   512      // timesteps
#define HH   1024     // hidden
#define JP   (HH/2)   // 512 j-pairs
#define NCTA 128      // persistent CTAs (1/SM, co-resident on 148 SMs)
#define NTHR 128      // 4 warps
#define MT   64       // batch tile per CTA
#define NT   32       // neuron tile per CTA
#define NPW  8        // neurons per warp (4 warps * 8 = 32)

// hidden state ping-pong, hidden-major pair-interleaved:
// g_h[buf][jp*BB + b] = (h[2*jp][b], h[2*jp+1][b])
__device__ float2 g_h[2][JP * BB];
// monotonic grid-barrier flags (zero-init; all equal after each launch -> replay-safe)
__device__ volatile int g_flags[NCTA];

__device__ __forceinline__ void fma2(unsigned long long& acc,
                                     unsigned long long a,
                                     unsigned long long b) {
    asm("fma.rn.f32x2 %0, %1, %2, %0;" : "+l"(acc) : "l"(a), "l"(b));
}
__device__ __forceinline__ float f2sum(unsigned long long a) {
    float lo, hi;
    asm("mov.b64 {%0, %1}, %2;" : "=f"(lo), "=f"(hi) : "l"(a));
    return lo + hi;
}

extern "C" __global__ void __launch_bounds__(NTHR, 1)
rnn_decoder_kernel(const float* __restrict__ init_in,   // [B,1]
                   const float* __restrict__ hidden0,   // [B,H]
                   const float* __restrict__ targets,   // [T,B,1]
                   const float* __restrict__ W_ih,      // [H,1]
                   const float* __restrict__ W_hh,      // [H,H]
                   const float* __restrict__ b_ih,      // [H]
                   const float* __restrict__ b_hh,      // [H]
                   const float* __restrict__ W_out,     // [1,H]
                   const float* __restrict__ b_out,     // [1]
                   float* __restrict__ out)             // [T,B,1]
{
    extern __shared__ float Ws[];          // [NT][HH] = 128 KB, resident all steps
    __shared__ float y_s[MT];

    const int tid  = threadIdx.x;
    const int cta  = blockIdx.x;
    const int m    = cta & 3;              // batch group
    const int n    = cta >> 2;             // neuron group
    const int b0   = m * MT;
    const int i0   = n * NT;
    const int lane = tid & 31;             // lane spans batch (contiguous!)
    const int wrp  = tid >> 5;
    const int iLoc = wrp * NPW;            // local neuron base (0,8,16,24)
    const int bA   = b0 + lane;
    const int bB   = bA + 32;

    const int base = g_flags[cta];
    int phase = 0;

    // ---- W_hh slice -> SMEM (coalesced float4) ----
    {
        const float4* src = reinterpret_cast<const float4*>(W_hh + (size_t)i0 * HH);
        float4* dst = reinterpret_cast<float4*>(Ws);
        for (int k = tid; k < NT * HH / 4; k += NTHR) dst[k] = src[k];
    }
    // per-thread constants for my 8 neurons
    float wih_r[NPW], bsum_r[NPW], wout_r[NPW];
#pragma unroll
    for (int q = 0; q < NPW; q++) {
        int i = i0 + iLoc + q;
        wih_r[q]  = W_ih[i];
        bsum_r[q] = b_ih[i] + b_hh[i];
        wout_r[q] = W_out[i];
    }
    const float bo = b_out[0];
#pragma unroll
    for (int k = 0; k < 8; k++) out[(size_t)cta * 1024 + k * NTHR + tid] = bo;

    // ---- transpose hidden0 [B][H] -> g_h[1] pair layout (one time) ----
    for (int e = cta * NTHR + tid; e < JP * BB; e += NCTA * NTHR) {
        int b  = e >> 9;          // /JP
        int jp = e & (JP - 1);
        float2 v = *reinterpret_cast<const float2*>(&hidden0[(size_t)b * HH + 2 * jp]);
        g_h[1][(size_t)jp * BB + b] = v;
    }

    // ---- grid barrier helpers (monotonic flags) ----
    auto arrive = [&]() {
        phase++;
        __syncthreads();
        if (tid == 0) { __threadfence(); g_flags[cta] = base + phase; }
    };
    auto wait = [&]() {
        if (tid < 32) {
            const int tgt = base + phase;
            bool ok;
            do {
                int a = g_flags[tid];
                int b = g_flags[tid + 32];
                int c = g_flags[tid + 64];
                int d = g_flags[tid + 96];
                ok = (a >= tgt) & (b >= tgt) & (c >= tgt) & (d >= tgt);
            } while (!__all_sync(0xffffffffu, ok));
            __threadfence();
        }
        __syncthreads();
    };

    arrive(); wait();   // Ws loaded, out initialized, transpose done — everywhere

    // u64 views of my 8 W rows (SMEM, broadcast reads)
    const unsigned long long* wr[NPW];
#pragma unroll
    for (int q = 0; q < NPW; q++)
        wr[q] = reinterpret_cast<const unsigned long long*>(Ws + (iLoc + q) * HH);

    const int jpOut = (i0 + iLoc) >> 1;    // output jp base for my neuron pairs

    for (int t = 0; t < TT; t++) {
        const float2* __restrict__ hsrc = g_h[(t + 1) & 1];  // t=0 -> g_h[1] (init)
        float2*       __restrict__ hdst = g_h[t & 1];
        const float* xsrc = (t == 0) ? init_in : (targets + (size_t)(t - 1) * BB);

        if (tid < MT) y_s[tid] = 0.f;

        const float x0 = xsrc[bA];
        const float x1 = xsrc[bB];

        const unsigned long long* __restrict__ HA =
            reinterpret_cast<const unsigned long long*>(hsrc) + bA;
        const unsigned long long* __restrict__ HB =
            reinterpret_cast<const unsigned long long*>(hsrc) + bB;

        unsigned long long accA[NPW], accB[NPW];
#pragma unroll
        for (int q = 0; q < NPW; q++) { accA[q] = 0ull; accB[q] = 0ull; }

#pragma unroll 4
        for (int jp = 0; jp < JP; jp += 2) {
            // coalesced 8B loads: lanes span contiguous batch -> 2 wavefronts each
            unsigned long long hA0 = HA[jp * BB];
            unsigned long long hB0 = HB[jp * BB];
            unsigned long long hA1 = HA[(jp + 1) * BB];
            unsigned long long hB1 = HB[(jp + 1) * BB];
#pragma unroll
            for (int q = 0; q < NPW; q++) {
                ulonglong2 w2 = *reinterpret_cast<const ulonglong2*>(wr[q] + jp);
                fma2(accA[q], hA0, w2.x);
                fma2(accA[q], hA1, w2.y);
                fma2(accB[q], hB0, w2.x);
                fma2(accB[q], hB1, w2.y);
            }
        }

        float h0v[NPW], h1v[NPW];
#pragma unroll
        for (int q = 0; q < NPW; q++) {
            h0v[q] = tanhf(fmaf(x0, wih_r[q], bsum_r[q]) + f2sum(accA[q]));
            h1v[q] = tanhf(fmaf(x1, wih_r[q], bsum_r[q]) + f2sum(accB[q]));
        }

        // store h' — neuron pairs -> coalesced STG.64
#pragma unroll
        for (int qp = 0; qp < NPW / 2; qp++) {
            hdst[(size_t)(jpOut + qp) * BB + bA] = make_float2(h0v[2 * qp], h0v[2 * qp + 1]);
            hdst[(size_t)(jpOut + qp) * BB + bB] = make_float2(h1v[2 * qp], h1v[2 * qp + 1]);
        }

        arrive();   // publish h' early; overlap epilogue with other CTAs

        // output projection partials (don't gate the next step's h reads)
        float p0 = 0.f, p1 = 0.f;
#pragma unroll
        for (int q = 0; q < NPW; q++) {
            p0 = fmaf(h0v[q], wout_r[q], p0);
            p1 = fmaf(h1v[q], wout_r[q], p1);
        }
        atomicAdd(&y_s[lane], p0);
        atomicAdd(&y_s[lane + 32], p1);
        __syncthreads();
        if (tid < MT) atomicAdd(&out[(size_t)t * BB + b0 + tid], y_s[tid]);

        wait();     // all CTAs' h' visible before step t+1
    }
}

extern "C" void kernel_launch(void* const* d_in, const int* in_sizes, int n_in,
                              void* d_out, int out_size) {
    const float* init_in = (const float*)d_in[0];
    const float* hidden0 = (const float*)d_in[1];
    const float* targets = (const float*)d_in[2];
    const float* W_ih    = (const float*)d_in[3];
    const float* W_hh    = (const float*)d_in[4];
    const float* b_ih    = (const float*)d_in[5];
    const float* b_hh    = (const float*)d_in[6];
    const float* W_out   = (const float*)d_in[7];
    const float* b_out   = (const float*)d_in[8];
    float* out = (float*)d_out;

    const size_t shmem = (size_t)NT * HH * sizeof(float);   // 128 KB
    cudaFuncSetAttribute(rnn_decoder_kernel,
                         cudaFuncAttributeMaxDynamicSharedMemorySize, (int)shmem);
    rnn_decoder_kernel<<<NCTA, NTHR, shmem>>>(init_in, hidden0, targets, W_ih,
                                              W_hh, b_ih, b_hh, W_out, b_out,
                                              out);
}

// round 4
// speedup vs baseline: 3.1149x; 1.2027x over previous
#include <cuda_runtime.h>
#include <math.h>

// ---------------- problem constants ----------------
#define BB   256      // batch
#define TT   512      // timesteps
#define HH   1024     // hidden
#define JP   (HH/2)   // 512 j-pairs
#define NCTA 128      // persistent CTAs (1/SM, co-resident)
#define NTHR 256      // 8 warps -> 2 per SMSP
#define MT   64       // batch tile per CTA
#define NT   32       // neuron tile per CTA
#define NPW  8        // neurons per thread

// hidden state ping-pong, hidden-major pair-interleaved:
// g_h[buf][jp*BB + b] = (h[2*jp][b], h[2*jp+1][b])
__device__ float2 g_h[2][JP * BB];
// monotonic grid-barrier flags (zero-init; all equal after each launch -> replay-safe)
__device__ volatile int g_flags[NCTA];

__device__ __forceinline__ void fma2(unsigned long long& acc,
                                     unsigned long long a,
                                     unsigned long long b) {
    asm("fma.rn.f32x2 %0, %1, %2, %0;" : "+l"(acc) : "l"(a), "l"(b));
}
__device__ __forceinline__ float f2sum(unsigned long long a) {
    float lo, hi;
    asm("mov.b64 {%0, %1}, %2;" : "=f"(lo), "=f"(hi) : "l"(a));
    return lo + hi;
}

extern "C" __global__ void __launch_bounds__(NTHR, 1)
rnn_decoder_kernel(const float* __restrict__ init_in,   // [B,1]
                   const float* __restrict__ hidden0,   // [B,H]
                   const float* __restrict__ targets,   // [T,B,1]
                   const float* __restrict__ W_ih,      // [H,1]
                   const float* __restrict__ W_hh,      // [H,H]
                   const float* __restrict__ b_ih,      // [H]
                   const float* __restrict__ b_hh,      // [H]
                   const float* __restrict__ W_out,     // [1,H]
                   const float* __restrict__ b_out,     // [1]
                   float* __restrict__ out)             // [T,B,1]
{
    extern __shared__ float Ws[];          // [NT][HH] = 128 KB, resident all steps
    __shared__ float y_s[MT];

    const int tid  = threadIdx.x;
    const int cta  = blockIdx.x;
    const int m    = cta & 3;              // batch group
    const int n    = cta >> 2;             // neuron group
    const int b0   = m * MT;
    const int i0   = n * NT;
    const int lane = tid & 31;             // lane spans batch (contiguous)
    const int wrp  = tid >> 5;             // 8 warps
    const int half = wrp >> 2;             // batch half (0/1)
    const int iLoc = (wrp & 3) * NPW;      // local neuron base (0,8,16,24)
    const int b    = b0 + half * 32 + lane;

    const int base = g_flags[cta];
    int phase = 0;

    // ---- W_hh slice -> SMEM (coalesced float4) ----
    {
        const float4* src = reinterpret_cast<const float4*>(W_hh + (size_t)i0 * HH);
        float4* dst = reinterpret_cast<float4*>(Ws);
        for (int k = tid; k < NT * HH / 4; k += NTHR) dst[k] = src[k];
    }
    // per-thread constants for my 8 neurons
    float wih_r[NPW], bsum_r[NPW], wout_r[NPW];
#pragma unroll
    for (int q = 0; q < NPW; q++) {
        int i = i0 + iLoc + q;
        wih_r[q]  = W_ih[i];
        bsum_r[q] = b_ih[i] + b_hh[i];
        wout_r[q] = W_out[i];
    }
    const float bo = b_out[0];
#pragma unroll
    for (int k = 0; k < 4; k++) out[(size_t)cta * 1024 + k * NTHR + tid] = bo;

    // ---- transpose hidden0 [B][H] -> g_h[1] pair layout (one time) ----
    for (int e = cta * NTHR + tid; e < JP * BB; e += NCTA * NTHR) {
        int bb = e >> 9;          // / JP
        int jp = e & (JP - 1);
        float2 v = *reinterpret_cast<const float2*>(&hidden0[(size_t)bb * HH + 2 * jp]);
        g_h[1][(size_t)jp * BB + bb] = v;
    }

    // ---- grid barrier helpers (monotonic flags) ----
    auto arrive = [&]() {
        phase++;
        __syncthreads();
        if (tid == 0) { __threadfence(); g_flags[cta] = base + phase; }
    };
    auto wait = [&]() {
        if (tid < 32) {
            const int tgt = base + phase;
            bool ok;
            do {
                int a = g_flags[tid];
                int c = g_flags[tid + 32];
                int d = g_flags[tid + 64];
                int e = g_flags[tid + 96];
                ok = (a >= tgt) & (c >= tgt) & (d >= tgt) & (e >= tgt);
            } while (!__all_sync(0xffffffffu, ok));
            __threadfence();
        }
        __syncthreads();
    };

    arrive(); wait();   // Ws loaded, out initialized, transpose done — everywhere

    // u64 views of my 8 W rows (SMEM broadcast reads)
    const unsigned long long* wr[NPW];
#pragma unroll
    for (int q = 0; q < NPW; q++)
        wr[q] = reinterpret_cast<const unsigned long long*>(Ws + (iLoc + q) * HH);

    const int jpOut = (i0 + iLoc) >> 1;    // output jp base for my neuron pairs

    for (int t = 0; t < TT; t++) {
        const float2* __restrict__ hsrc = g_h[(t + 1) & 1];  // t=0 -> g_h[1]
        float2*       __restrict__ hdst = g_h[t & 1];
        const float* xsrc = (t == 0) ? init_in : (targets + (size_t)(t - 1) * BB);

        if (tid < MT) y_s[tid] = 0.f;

        const float x = xsrc[b];

        const unsigned long long* __restrict__ HP =
            reinterpret_cast<const unsigned long long*>(hsrc) + b;

        unsigned long long acc[NPW];
#pragma unroll
        for (int q = 0; q < NPW; q++) acc[q] = 0ull;

#pragma unroll 8
        for (int jp = 0; jp < JP; jp += 2) {
            unsigned long long h0 = HP[jp * BB];          // coalesced LDG.64
            unsigned long long h1 = HP[(jp + 1) * BB];
#pragma unroll
            for (int q = 0; q < NPW; q++) {
                ulonglong2 w2 = *reinterpret_cast<const ulonglong2*>(wr[q] + jp);
                fma2(acc[q], h0, w2.x);
                fma2(acc[q], h1, w2.y);
            }
        }

        float hv[NPW];
#pragma unroll
        for (int q = 0; q < NPW; q++)
            hv[q] = tanhf(fmaf(x, wih_r[q], bsum_r[q]) + f2sum(acc[q]));

        // store h' — neuron pairs -> coalesced STG.64
#pragma unroll
        for (int qp = 0; qp < NPW / 2; qp++)
            hdst[(size_t)(jpOut + qp) * BB + b] = make_float2(hv[2 * qp], hv[2 * qp + 1]);

        arrive();   // publish h' early; epilogue overlaps other CTAs' waits

        // output projection partials
        float p = 0.f;
#pragma unroll
        for (int q = 0; q < NPW; q++) p = fmaf(hv[q], wout_r[q], p);
        atomicAdd(&y_s[half * 32 + lane], p);
        __syncthreads();
        if (tid < MT) atomicAdd(&out[(size_t)t * BB + b0 + tid], y_s[tid]);

        wait();     // all CTAs' h' visible before step t+1
    }
}

extern "C" void kernel_launch(void* const* d_in, const int* in_sizes, int n_in,
                              void* d_out, int out_size) {
    const float* init_in = (const float*)d_in[0];
    const float* hidden0 = (const float*)d_in[1];
    const float* targets = (const float*)d_in[2];
    const float* W_ih    = (const float*)d_in[3];
    const float* W_hh    = (const float*)d_in[4];
    const float* b_ih    = (const float*)d_in[5];
    const float* b_hh    = (const float*)d_in[6];
    const float* W_out   = (const float*)d_in[7];
    const float* b_out   = (const float*)d_in[8];
    float* out = (float*)d_out;

    const size_t shmem = (size_t)NT * HH * sizeof(float);   // 128 KB
    cudaFuncSetAttribute(rnn_decoder_kernel,
                         cudaFuncAttributeMaxDynamicSharedMemorySize, (int)shmem);
    rnn_decoder_kernel<<<NCTA, NTHR, shmem>>>(init_in, hidden0, targets, W_ih,
                                              W_hh, b_ih, b_hh, W_out, b_out,
                                              out);
}

// round 6
// speedup vs baseline: 3.1856x; 1.0227x over previous
#include <cuda_runtime.h>
#include <cuda_bf16.h>
#include <math.h>
#include <stdint.h>

// ---------------- problem constants ----------------
#define BB   256
#define TT   512
#define HH   1024
#define NCTA 128
#define NTHR 256      // 8 warps: 4 along M x 2 along N

// phase-1 tiling: 8 Mtiles(128 neurons) x 4 Ktiles(256) x 4 Btiles(64 batch)
// SMEM: A (W frags, hi+lo) 128 KB resident | B (h frags, hi+lo) 64 KB restaged
#define OFF_B   (128 * 1024)
#define SMEM_SZ (OFF_B + 64 * 1024)     // 192 KB

// ---------------- device globals ----------------
__device__ __align__(16) __nv_bfloat16 g_hhi[BB * HH];   // h hi   [b][n]
__device__ __align__(16) __nv_bfloat16 g_hlo[BB * HH];   // h lo   [b][n]
// K-partials: idx = ((ktq*4+nb)*32 + (n>>5))*2048 + c*32 + (n&31)
__device__ float g_p4[4 * 4 * 32 * 2048];                // 4 MB
__device__ volatile int g_flags[NCTA];                   // monotonic barrier flags

__device__ __forceinline__ uint32_t pack_bf(float x, float y) {
    __nv_bfloat162 v = __floats2bfloat162_rn(x, y);      // low = x, high = y
    return *reinterpret_cast<uint32_t*>(&v);
}
__device__ __forceinline__ void mma16816(float* c, const uint32_t* a,
                                         const uint32_t* b) {
    asm volatile(
        "mma.sync.aligned.m16n8k16.row.col.f32.bf16.bf16.f32 "
        "{%0,%1,%2,%3}, {%4,%5,%6,%7}, {%8,%9}, {%0,%1,%2,%3};"
        : "+f"(c[0]), "+f"(c[1]), "+f"(c[2]), "+f"(c[3])
        : "r"(a[0]), "r"(a[1]), "r"(a[2]), "r"(a[3]), "r"(b[0]), "r"(b[1]));
}

extern "C" __global__ void __launch_bounds__(NTHR, 1)
rnn_decoder_kernel(const float* __restrict__ init_in,   // [B,1]
                   const float* __restrict__ hidden0,   // [B,H]
                   const float* __restrict__ targets,   // [T,B,1]
                   const float* __restrict__ W_ih,      // [H,1]
                   const float* __restrict__ W_hh,      // [H,H]
                   const float* __restrict__ b_ih,      // [H]
                   const float* __restrict__ b_hh,      // [H]
                   const float* __restrict__ W_out,     // [1,H]
                   const float* __restrict__ b_out,     // [1]
                   float* __restrict__ out)             // [T,B,1]
{
    extern __shared__ __align__(16) char smem[];

    const int tid  = threadIdx.x;
    const int cta  = blockIdx.x;
    const int wid  = tid >> 5;
    const int lane = tid & 31;
    const int g    = lane >> 2;          // 0..7
    const int tq   = lane & 3;           // 0..3
    const int wm   = wid >> 1;           // 0..3 (M split, 32 rows each)
    const int wn   = wid & 1;            // 0..1 (N split, 32 cols each)

    // phase-1 role
    const int mi  = cta & 7;
    const int ktq = (cta >> 3) & 3;
    const int nb  = cta >> 5;
    const int m0  = mi * 128;
    const int k0  = ktq * 256;
    const int bb0 = nb * 64;

    // phase-2 role: 128 neurons x 16 batches per CTA
    const int n0p = (cta & 7) * 128;
    const int b0p = (cta >> 3) * 16;

    const int base = g_flags[cta];
    int phase = 0;

    // ---- one-time: W fragments (hi+lo) -> SMEM, exact mma lane order ----
    // layout: byte = wm*32768 + p*16384 + kk*1024 + u*512 + lane*16
    if (wn == 0) {
        for (int kk = 0; kk < 16; kk++) {
#pragma unroll
            for (int u = 0; u < 2; u++) {
                const int r0 = m0 + wm * 32 + u * 16 + g;
                const int r1 = r0 + 8;
                const int c  = k0 + kk * 16 + 2 * tq;
                float w00 = W_hh[(size_t)r0 * HH + c];
                float w01 = W_hh[(size_t)r0 * HH + c + 1];
                float w04 = W_hh[(size_t)r0 * HH + c + 8];
                float w05 = W_hh[(size_t)r0 * HH + c + 9];
                float w10 = W_hh[(size_t)r1 * HH + c];
                float w11 = W_hh[(size_t)r1 * HH + c + 1];
                float w14 = W_hh[(size_t)r1 * HH + c + 8];
                float w15 = W_hh[(size_t)r1 * HH + c + 9];
                uint4 hi, lo;
                hi.x = pack_bf(w00, w01);
                hi.y = pack_bf(w10, w11);
                hi.z = pack_bf(w04, w05);
                hi.w = pack_bf(w14, w15);
                lo.x = pack_bf(w00 - __bfloat162float(__float2bfloat16(w00)),
                               w01 - __bfloat162float(__float2bfloat16(w01)));
                lo.y = pack_bf(w10 - __bfloat162float(__float2bfloat16(w10)),
                               w11 - __bfloat162float(__float2bfloat16(w11)));
                lo.z = pack_bf(w04 - __bfloat162float(__float2bfloat16(w04)),
                               w05 - __bfloat162float(__float2bfloat16(w05)));
                lo.w = pack_bf(w14 - __bfloat162float(__float2bfloat16(w14)),
                               w15 - __bfloat162float(__float2bfloat16(w15)));
                const int ob = wm * 32768 + kk * 1024 + u * 512 + lane * 16;
                *reinterpret_cast<uint4*>(smem + ob)         = hi;
                *reinterpret_cast<uint4*>(smem + ob + 16384) = lo;
            }
        }
    }

    // ---- one-time: hidden0 -> bf16 hi/lo split (slice of 2048) ----
    for (int i = tid; i < 2048; i += NTHR) {
        int e = cta * 2048 + i;
        float v = hidden0[e];
        __nv_bfloat16 hi = __float2bfloat16(v);
        g_hhi[e] = hi;
        g_hlo[e] = __float2bfloat16(v - __bfloat162float(hi));
    }
    // ---- one-time: out init to b_out ----
    {
        const float bo = b_out[0];
        for (int i = tid; i < 1024; i += NTHR) out[(size_t)cta * 1024 + i] = bo;
    }

    // phase-2 per-thread constants
    float wih_r[4], bsum_r[4], wout_r[4];
    int   qoff[4], nidx[4];
#pragma unroll
    for (int nc = 0; nc < 4; nc++) {
        int n = n0p + nc * 32 + lane;
        nidx[nc]   = n;
        wih_r[nc]  = W_ih[n];
        bsum_r[nc] = b_ih[n] + b_hh[n];
        wout_r[nc] = W_out[n];
        qoff[nc]   = (n >> 5) * 2048 + lane;
    }

    // ---- grid barrier (monotonic flags; proven in R3/R4) ----
    auto gbar = [&]() {
        phase++;
        __syncthreads();
        if (tid == 0) { __threadfence(); g_flags[cta] = base + phase; }
        if (tid < 32) {
            const int tgt = base + phase;
            bool ok;
            do {
                int a = g_flags[tid];
                int b = g_flags[tid + 32];
                int c = g_flags[tid + 64];
                int d = g_flags[tid + 96];
                ok = (a >= tgt) & (b >= tgt) & (c >= tgt) & (d >= tgt);
            } while (!__all_sync(0xffffffffu, ok));
            __threadfence();
        }
        __syncthreads();
    };

    gbar();   // W frags in SMEM, h split published, out initialized

    // B staging constants: thread covers (batch nloc, k-nibble t4) for all 16 kk
    const int nloc = tid >> 2;
    const int t4   = tid & 3;
    const int sgg  = nloc & 7;
    const int nt8s = nloc >> 3;
    const int slot = t4 >> 1;
    const int tA   = (t4 & 1) * 2;
    const uint32_t bsm = OFF_B + nt8s * 256 + (sgg * 4 + tA) * 8 + slot * 4;
    const size_t   gB  = (size_t)(bb0 + nloc) * HH + k0 + t4 * 4;

    const int pb = ((ktq * 4 + nb) * 32 + mi * 4 + wm) * 2048;   // g_p4 base

    for (int t = 0; t < TT; t++) {
        // ---- stage B (h) fragments: hi and lo, L2-fresh ----
#pragma unroll 4
        for (int j = 0; j < 16; j++) {
            uint2 vh = __ldcg(reinterpret_cast<const uint2*>(g_hhi + gB + 16 * j));
            uint2 vl = __ldcg(reinterpret_cast<const uint2*>(g_hlo + gB + 16 * j));
            *reinterpret_cast<uint32_t*>(smem + bsm + j * 2048)           = vh.x;
            *reinterpret_cast<uint32_t*>(smem + bsm + j * 2048 + 8)       = vh.y;
            *reinterpret_cast<uint32_t*>(smem + bsm + 32768 + j * 2048)     = vl.x;
            *reinterpret_cast<uint32_t*>(smem + bsm + 32768 + j * 2048 + 8) = vl.y;
        }
        __syncthreads();

        // ---- MMA mainloop: warp computes m32 x n32, K=256, 3 passes ----
        float acc[2][4][4];
#pragma unroll
        for (int u = 0; u < 2; u++)
#pragma unroll
            for (int nt = 0; nt < 4; nt++)
#pragma unroll
                for (int e = 0; e < 4; e++) acc[u][nt][e] = 0.f;

#pragma unroll 2
        for (int kk = 0; kk < 16; kk++) {
            const int ab = wm * 32768 + kk * 1024 + lane * 16;
            uint4 Ahi0 = *reinterpret_cast<const uint4*>(smem + ab);
            uint4 Ahi1 = *reinterpret_cast<const uint4*>(smem + ab + 512);
            uint4 Alo0 = *reinterpret_cast<const uint4*>(smem + ab + 16384);
            uint4 Alo1 = *reinterpret_cast<const uint4*>(smem + ab + 16384 + 512);
#pragma unroll
            for (int nt = 0; nt < 4; nt++) {
                const int bb = OFF_B + kk * 2048 + (wn * 4 + nt) * 256 + lane * 8;
                uint2 Bhi = *reinterpret_cast<const uint2*>(smem + bb);
                uint2 Blo = *reinterpret_cast<const uint2*>(smem + bb + 32768);
                mma16816(acc[0][nt], &Ahi0.x, &Bhi.x);
                mma16816(acc[1][nt], &Ahi1.x, &Bhi.x);
                mma16816(acc[0][nt], &Alo0.x, &Bhi.x);
                mma16816(acc[1][nt], &Alo1.x, &Bhi.x);
                mma16816(acc[0][nt], &Ahi0.x, &Blo.x);
                mma16816(acc[1][nt], &Ahi1.x, &Blo.x);
            }
        }

        // ---- D writeback: lane-interleaved partial layout ----
#pragma unroll
        for (int u = 0; u < 2; u++) {
            const int r = u * 16 + g;
#pragma unroll
            for (int nt = 0; nt < 4; nt++) {
                const int cb = wn * 32 + nt * 8 + 2 * tq;
                g_p4[pb + cb * 32 + r]           = acc[u][nt][0];
                g_p4[pb + (cb + 1) * 32 + r]     = acc[u][nt][1];
                g_p4[pb + cb * 32 + r + 8]       = acc[u][nt][2];
                g_p4[pb + (cb + 1) * 32 + r + 8] = acc[u][nt][3];
            }
        }

        gbar();   // all K-partials visible

        // ---- phase 2: reduce 4 K-partials, bias+x, tanh, re-split, y ----
        const float* xsrc = (t == 0) ? init_in : (targets + (size_t)(t - 1) * BB);
#pragma unroll
        for (int bbq = 0; bbq < 2; bbq++) {
            const int b   = b0p + wid * 2 + bbq;
            const int nbb = b >> 6;
            const int c   = b & 63;
            const float x = xsrc[b];
            const int r2  = nbb * 65536 + c * 32;
            float ysum = 0.f;
#pragma unroll
            for (int nc = 0; nc < 4; nc++) {
                const int q = r2 + qoff[nc];
                float s = __ldcg(&g_p4[q]) +
                          __ldcg(&g_p4[q + 262144]) +
                          __ldcg(&g_p4[q + 524288]) +
                          __ldcg(&g_p4[q + 786432]);
                s += fmaf(x, wih_r[nc], bsum_r[nc]);
                float hv = tanhf(s);
                __nv_bfloat16 hi = __float2bfloat16(hv);
                const size_t gg2 = (size_t)b * HH + nidx[nc];
                g_hhi[gg2] = hi;
                g_hlo[gg2] = __float2bfloat16(hv - __bfloat162float(hi));
                ysum = fmaf(hv, wout_r[nc], ysum);
            }
#pragma unroll
            for (int o = 16; o > 0; o >>= 1)
                ysum += __shfl_xor_sync(0xffffffffu, ysum, o);
            if (lane == 0) atomicAdd(&out[(size_t)t * BB + b], ysum);
        }

        gbar();   // h split published before next step's B staging
    }
}

extern "C" void kernel_launch(void* const* d_in, const int* in_sizes, int n_in,
                              void* d_out, int out_size) {
    const float* init_in = (const float*)d_in[0];
    const float* hidden0 = (const float*)d_in[1];
    const float* targets = (const float*)d_in[2];
    const float* W_ih    = (const float*)d_in[3];
    const float* W_hh    = (const float*)d_in[4];
    const float* b_ih    = (const float*)d_in[5];
    const float* b_hh    = (const float*)d_in[6];
    const float* W_out   = (const float*)d_in[7];
    const float* b_out   = (const float*)d_in[8];
    float* out = (float*)d_out;

    cudaFuncSetAttribute(rnn_decoder_kernel,
                         cudaFuncAttributeMaxDynamicSharedMemorySize, SMEM_SZ);
    rnn_decoder_kernel<<<NCTA, NTHR, SMEM_SZ>>>(init_in, hidden0, targets, W_ih,
                                                W_hh, b_ih, b_hh, W_out, b_out,
                                                out);
}

// round 7
// speedup vs baseline: 5.1833x; 1.6271x over previous
#include <cuda_runtime.h>
#include <cuda_bf16.h>
#include <math.h>
#include <stdint.h>

// ---------------- problem constants ----------------
#define BB   256
#define TT   512
#define HH   1024
#define NCTA 128
#define NTHR 512      // 16 warps: 8 along M x 2 along N

// SMEM: A frags (W hi+lo) 128 KB resident | B frags (h hi+lo) 64 KB | consts
#define OFF_AHI 0
#define OFF_ALO (64 * 1024)
#define OFF_BHI (128 * 1024)
#define OFF_BLO (160 * 1024)
#define OFF_CST (192 * 1024)
#define SMEM_SZ (OFF_CST + 3 * 1024)

// ---------------- device globals ----------------
// partial preactivations, ping-pong: [buf 2][ktq 4][b 256][n 1024]
__device__ float g_p4[2 * 4 * 256 * 1024];               // 8 MB
__device__ volatile int g_done[NCTA];                    // producer step flags
__device__ volatile int g_ack[NCTA];                     // consumer ack flags
__device__ volatile int g_flags[NCTA];                   // one-time init barrier

__device__ __forceinline__ uint32_t pack_bf(float x, float y) {
    __nv_bfloat162 v = __floats2bfloat162_rn(x, y);      // low = x, high = y
    return *reinterpret_cast<uint32_t*>(&v);
}
__device__ __forceinline__ void mma16816(float* c, const uint32_t* a,
                                         const uint32_t* b) {
    asm volatile(
        "mma.sync.aligned.m16n8k16.row.col.f32.bf16.bf16.f32 "
        "{%0,%1,%2,%3}, {%4,%5,%6,%7}, {%8,%9}, {%0,%1,%2,%3};"
        : "+f"(c[0]), "+f"(c[1]), "+f"(c[2]), "+f"(c[3])
        : "r"(a[0]), "r"(a[1]), "r"(a[2]), "r"(a[3]), "r"(b[0]), "r"(b[1]));
}
__device__ __forceinline__ float ftanh(float x) {
    // tanh(x) = 1 - 2/(e^{2x}+1); MUFU-based, rel err ~2e-7, inf-safe both ends
    float e = __expf(2.f * x);
    return 1.f - __fdividef(2.f, e + 1.f);
}

extern "C" __global__ void __launch_bounds__(NTHR, 1)
rnn_decoder_kernel(const float* __restrict__ init_in,   // [B,1]
                   const float* __restrict__ hidden0,   // [B,H]
                   const float* __restrict__ targets,   // [T,B,1]
                   const float* __restrict__ W_ih,      // [H,1]
                   const float* __restrict__ W_hh,      // [H,H]
                   const float* __restrict__ b_ih,      // [H]
                   const float* __restrict__ b_hh,      // [H]
                   const float* __restrict__ W_out,     // [1,H]
                   const float* __restrict__ b_out,     // [1]
                   float* __restrict__ out)             // [T,B,1]
{
    extern __shared__ __align__(16) char smem[];
    float* wout_s = reinterpret_cast<float*>(smem + OFF_CST);
    float* wih_s  = wout_s + 256;
    float* bias_s = wout_s + 512;

    const int tid  = threadIdx.x;
    const int cta  = blockIdx.x;
    const int wid  = tid >> 5;
    const int lane = tid & 31;
    const int g    = lane >> 2;
    const int tq   = lane & 3;
    const int wmq  = wid >> 1;           // 0..7: M sub-tile (16 rows)
    const int wn   = wid & 1;            // 0..1: N half (32 cols)
    const int bth  = tid >> 3;           // 0..63: batch col (phase 2 / staging)
    const int oct  = tid & 7;            // k-octet
    const int tqb  = oct & 3;
    const int slb  = oct >> 2;

    const int mi  = cta & 7;
    const int ktq = (cta >> 3) & 3;
    const int nb  = cta >> 5;
    const int m0  = mi * 128;
    const int k0  = ktq * 256;
    const int bb0 = nb * 64;

    const int base_g = g_flags[cta];
    const int base_d = g_done[cta];
    const int base_a = g_ack[cta];

    // my 8 producers (partials for n in my k-range) / 8 readers (of my region)
    int pidx = cta, ridx = cta;          // lanes >= 8 poll own flag (always ok)
    if (lane < 8) {
        pidx = (2 * ktq + (lane & 1)) + 8 * (lane >> 1) + 32 * nb;
        ridx = lane + 8 * (mi >> 1) + 32 * nb;
    }

    // ---- one-time: per-n constants for my k-range (phase-2 neurons) ----
    if (tid < 256) {
        const int n = k0 + tid;
        wout_s[tid] = W_out[n];
        wih_s[tid]  = W_ih[n];
        bias_s[tid] = b_ih[n] + b_hh[n];
    }

    // ---- one-time: W fragments (hi+lo) -> SMEM in exact mma lane order ----
    if (wid < 8) {
        const int r0 = m0 + wid * 16 + g;
        const int r1 = r0 + 8;
        for (int kk = 0; kk < 16; kk++) {
            const int c = k0 + kk * 16 + 2 * tq;
            float w00 = W_hh[(size_t)r0 * HH + c];
            float w01 = W_hh[(size_t)r0 * HH + c + 1];
            float w04 = W_hh[(size_t)r0 * HH + c + 8];
            float w05 = W_hh[(size_t)r0 * HH + c + 9];
            float w10 = W_hh[(size_t)r1 * HH + c];
            float w11 = W_hh[(size_t)r1 * HH + c + 1];
            float w14 = W_hh[(size_t)r1 * HH + c + 8];
            float w15 = W_hh[(size_t)r1 * HH + c + 9];
            uint4 hi, lo;
            hi.x = pack_bf(w00, w01);
            hi.y = pack_bf(w10, w11);
            hi.z = pack_bf(w04, w05);
            hi.w = pack_bf(w14, w15);
            lo.x = pack_bf(w00 - __bfloat162float(__float2bfloat16(w00)),
                           w01 - __bfloat162float(__float2bfloat16(w01)));
            lo.y = pack_bf(w10 - __bfloat162float(__float2bfloat16(w10)),
                           w11 - __bfloat162float(__float2bfloat16(w11)));
            lo.z = pack_bf(w04 - __bfloat162float(__float2bfloat16(w04)),
                           w05 - __bfloat162float(__float2bfloat16(w05)));
            lo.w = pack_bf(w14 - __bfloat162float(__float2bfloat16(w14)),
                           w15 - __bfloat162float(__float2bfloat16(w15)));
            const int ob = (wid * 16 + kk) * 512 + lane * 16;
            *reinterpret_cast<uint4*>(smem + OFF_AHI + ob) = hi;
            *reinterpret_cast<uint4*>(smem + OFF_ALO + ob) = lo;
        }
    }

    // ---- one-time: B fragments from hidden0 (h_0 for my k-range x batch) ----
    const int sts = (bth >> 3) * 256 + ((bth & 7) * 4 + tqb) * 8 + slb * 4;
    {
#pragma unroll 4
        for (int kk = 0; kk < 16; kk++) {
            const int nl = kk * 16 + 2 * tqb + 8 * slb;
            float2 v = *reinterpret_cast<const float2*>(
                &hidden0[(size_t)(bb0 + bth) * HH + k0 + nl]);
            __nv_bfloat16 bx = __float2bfloat16(v.x);
            __nv_bfloat16 by = __float2bfloat16(v.y);
            uint32_t uhi = (uint32_t)__bfloat16_as_ushort(bx) |
                           ((uint32_t)__bfloat16_as_ushort(by) << 16);
            uint32_t ulo = pack_bf(v.x - __bfloat162float(bx),
                                   v.y - __bfloat162float(by));
            *reinterpret_cast<uint32_t*>(smem + OFF_BHI + kk * 2048 + sts) = uhi;
            *reinterpret_cast<uint32_t*>(smem + OFF_BLO + kk * 2048 + sts) = ulo;
        }
    }

    // ---- one-time: out init to b_out (atomicAdd target) ----
    {
        const float bo = b_out[0];
        out[(size_t)cta * 1024 + tid]       = bo;
        out[(size_t)cta * 1024 + 512 + tid] = bo;
    }

    // ---- one-time full grid barrier (out init complete everywhere) ----
    __threadfence();
    __syncthreads();
    if (tid == 0) g_flags[cta] = base_g + 1;
    if (tid < 32) {
        const int tgt = base_g + 1;
        bool ok;
        do {
            int a = g_flags[tid];
            int b = g_flags[tid + 32];
            int c = g_flags[tid + 64];
            int d = g_flags[tid + 96];
            ok = (a >= tgt) & (b >= tgt) & (c >= tgt) & (d >= tgt);
        } while (!__all_sync(0xffffffffu, ok));
        __threadfence();
    }
    __syncthreads();

#pragma unroll 1
    for (int t = 0; t < TT; t++) {
        // ---- MMA: warp m16 x n32, K=256, 3 bf16-split passes ----
        float acc[4][4];
#pragma unroll
        for (int nt = 0; nt < 4; nt++)
#pragma unroll
            for (int e = 0; e < 4; e++) acc[nt][e] = 0.f;

#pragma unroll 4
        for (int kk = 0; kk < 16; kk++) {
            const int ab = (wmq * 16 + kk) * 512 + lane * 16;
            uint4 Ah = *reinterpret_cast<const uint4*>(smem + OFF_AHI + ab);
            uint4 Al = *reinterpret_cast<const uint4*>(smem + OFF_ALO + ab);
#pragma unroll
            for (int nt = 0; nt < 4; nt++) {
                const int bb = kk * 2048 + (wn * 4 + nt) * 256 + lane * 8;
                uint2 Bh = *reinterpret_cast<const uint2*>(smem + OFF_BHI + bb);
                uint2 Bl = *reinterpret_cast<const uint2*>(smem + OFF_BLO + bb);
                mma16816(acc[nt], &Ah.x, &Bh.x);
                mma16816(acc[nt], &Al.x, &Bh.x);
                mma16816(acc[nt], &Ah.x, &Bl.x);
            }
        }

        // ---- back-pressure: readers of buf[t&1] finished step t-2 ----
        if (t >= 2 && wid == 0) {
            const int tgt = base_a + t - 1;
            bool ok;
            do { ok = (g_ack[ridx] >= tgt); } while (!__all_sync(0xffffffffu, ok));
        }
        __syncthreads();   // also: all MMA smem reads done before later B-frag STS

        // ---- writeback partials -> g_p4[t&1][ktq][b][n] (full 32B sectors) ----
        {
            float* buf = g_p4 + (size_t)(t & 1) * 1048576 + (size_t)ktq * 262144;
            const int rl = m0 + wmq * 16 + g;
#pragma unroll
            for (int nt = 0; nt < 4; nt++) {
                const int bc = bb0 + wn * 32 + nt * 8 + 2 * tq;
                __stcg(&buf[(size_t)bc * 1024 + rl],           acc[nt][0]);
                __stcg(&buf[(size_t)(bc + 1) * 1024 + rl],     acc[nt][1]);
                __stcg(&buf[(size_t)bc * 1024 + rl + 8],       acc[nt][2]);
                __stcg(&buf[(size_t)(bc + 1) * 1024 + rl + 8], acc[nt][3]);
            }
        }
        __threadfence();
        __syncthreads();
        if (tid == 0) g_done[cta] = base_d + t + 1;

        // ---- wait for my 8 producers ----
        if (wid == 0) {
            const int tgt = base_d + t + 1;
            bool ok;
            do { ok = (g_done[pidx] >= tgt); } while (!__all_sync(0xffffffffu, ok));
            __threadfence();
        }
        __syncthreads();

        // ---- fused phase 2: reduce 4 planes, tanh, pack next B frags, y ----
        const float xv = (t == 0) ? init_in[bb0 + bth]
                                  : targets[(size_t)(t - 1) * BB + bb0 + bth];
        const float* q0 = g_p4 + (size_t)(t & 1) * 1048576 +
                          (size_t)(bb0 + bth) * 1024 + k0;
        float ysum = 0.f;
#pragma unroll 4
        for (int kk = 0; kk < 16; kk++) {
            const int nl = kk * 16 + 2 * tqb + 8 * slb;
            float2 s0 = __ldcg(reinterpret_cast<const float2*>(q0 + nl));
            float2 s1 = __ldcg(reinterpret_cast<const float2*>(q0 + 262144 + nl));
            float2 s2 = __ldcg(reinterpret_cast<const float2*>(q0 + 524288 + nl));
            float2 s3 = __ldcg(reinterpret_cast<const float2*>(q0 + 786432 + nl));
            float2 wi = *reinterpret_cast<const float2*>(&wih_s[nl]);
            float2 bs = *reinterpret_cast<const float2*>(&bias_s[nl]);
            float px = ((s0.x + s1.x) + (s2.x + s3.x)) + fmaf(xv, wi.x, bs.x);
            float py = ((s0.y + s1.y) + (s2.y + s3.y)) + fmaf(xv, wi.y, bs.y);
            float hx = ftanh(px);
            float hy = ftanh(py);
            if (mi == 0) {
                float2 wo = *reinterpret_cast<const float2*>(&wout_s[nl]);
                ysum += hx * wo.x + hy * wo.y;
            }
            __nv_bfloat16 bx = __float2bfloat16(hx);
            __nv_bfloat16 by = __float2bfloat16(hy);
            uint32_t uhi = (uint32_t)__bfloat16_as_ushort(bx) |
                           ((uint32_t)__bfloat16_as_ushort(by) << 16);
            uint32_t ulo = pack_bf(hx - __bfloat162float(bx),
                                   hy - __bfloat162float(by));
            *reinterpret_cast<uint32_t*>(smem + OFF_BHI + kk * 2048 + sts) = uhi;
            *reinterpret_cast<uint32_t*>(smem + OFF_BLO + kk * 2048 + sts) = ulo;
        }
        if (mi == 0) {   // one mi-group per (ktq, nb) emits the y partial
            ysum += __shfl_xor_sync(0xffffffffu, ysum, 1);
            ysum += __shfl_xor_sync(0xffffffffu, ysum, 2);
            ysum += __shfl_xor_sync(0xffffffffu, ysum, 4);
            if (oct == 0) atomicAdd(&out[(size_t)t * BB + bb0 + bth], ysum);
        }
        __syncthreads();   // B frags published; partial reads complete
        if (tid == 0) g_ack[cta] = base_a + t + 1;
    }
}

extern "C" void kernel_launch(void* const* d_in, const int* in_sizes, int n_in,
                              void* d_out, int out_size) {
    const float* init_in = (const float*)d_in[0];
    const float* hidden0 = (const float*)d_in[1];
    const float* targets = (const float*)d_in[2];
    const float* W_ih    = (const float*)d_in[3];
    const float* W_hh    = (const float*)d_in[4];
    const float* b_ih    = (const float*)d_in[5];
    const float* b_hh    = (const float*)d_in[6];
    const float* W_out   = (const float*)d_in[7];
    const float* b_out   = (const float*)d_in[8];
    float* out = (float*)d_out;

    cudaFuncSetAttribute(rnn_decoder_kernel,
                         cudaFuncAttributeMaxDynamicSharedMemorySize, SMEM_SZ);
    rnn_decoder_kernel<<<NCTA, NTHR, SMEM_SZ>>>(init_in, hidden0, targets, W_ih,
                                                W_hh, b_ih, b_hh, W_out, b_out,
                                                out);
}